// round 15
// baseline (speedup 1.0000x reference)
#include <cuda_runtime.h>
#include <cuda_fp16.h>
#include <cstdint>

// Problem constants
#define B_DIM 16384
#define S_DIM 512
#define NS    2048   // 4*S
#define KTOT  1024   // 2*S (x-half + recurrent-half)
#define BS    (B_DIM * S_DIM)  // 8388608

// ---------------------------------------------------------------------------
// Device scratch (static __device__: allocation-guard safe)
// ---------------------------------------------------------------------------
__device__ float g_z[(size_t)B_DIM * NS];                 // 128 MiB (permuted cols)
__device__ __half g_Ah[(size_t)B_DIM * KTOT];             // 32 MiB
__device__ __half g_Al[(size_t)B_DIM * KTOT];             // 32 MiB
__device__ __half g_Bh[(size_t)2 * NS * KTOT];            // 8 MiB  per-layer [Nperm,K]

// ---------------------------------------------------------------------------
// PTX helpers — sm_80+ features only (compute_103 virtual target safe)
// ---------------------------------------------------------------------------
__device__ __forceinline__ uint32_t smem_u32(const void* p) {
    uint32_t a;
    asm("{ .reg .u64 t; cvta.to.shared.u64 t, %1; cvt.u32.u64 %0, t; }"
        : "=r"(a) : "l"(p));
    return a;
}

#define CP_ASYNC16(dst_u32, src_ptr) \
    asm volatile("cp.async.cg.shared.global [%0], [%1], 16;" \
                 :: "r"((uint32_t)(dst_u32)), "l"((const void*)(src_ptr)) : "memory")
#define CP_COMMIT() asm volatile("cp.async.commit_group;" ::: "memory")
#define CP_WAIT1()  asm volatile("cp.async.wait_group 1;" ::: "memory")
#define CP_WAIT0()  asm volatile("cp.async.wait_group 0;" ::: "memory")

// SW128 swizzle on byte offset within a 1024-aligned tile (128B rows)
#define SWZ(o) ((o) ^ (((o) >> 3) & 0x70))

#define LDSM_X4(r, addr) \
    asm volatile("ldmatrix.sync.aligned.m8n8.x4.shared.b16 {%0,%1,%2,%3}, [%4];" \
                 : "=r"((r)[0]), "=r"((r)[1]), "=r"((r)[2]), "=r"((r)[3]) \
                 : "r"((uint32_t)(addr)))

#define MMA16816(d, a, b0, b1) \
    asm volatile("mma.sync.aligned.m16n8k16.row.col.f32.f16.f16.f32 " \
                 "{%0,%1,%2,%3}, {%4,%5,%6,%7}, {%8,%9}, {%0,%1,%2,%3};" \
                 : "+f"((d)[0]), "+f"((d)[1]), "+f"((d)[2]), "+f"((d)[3]) \
                 : "r"((a)[0]), "r"((a)[1]), "r"((a)[2]), "r"((a)[3]), \
                   "r"(b0), "r"(b1))

__device__ __forceinline__ float sigf(float x) { return 1.f / (1.f + expf(-x)); }

// ---------------------------------------------------------------------------
// Conversion kernels (fp16 hi/lo split for A; fp16 truncation for B)
// ---------------------------------------------------------------------------
__device__ __forceinline__ void split4_store(float4 v, __half* ph, __half* pl) {
    __half h0 = __float2half_rn(v.x);
    __half h1 = __float2half_rn(v.y);
    __half h2 = __float2half_rn(v.z);
    __half h3 = __float2half_rn(v.w);
    __half l0 = __float2half_rn(v.x - __half2float(h0));
    __half l1 = __float2half_rn(v.y - __half2float(h1));
    __half l2 = __float2half_rn(v.z - __half2float(h2));
    __half l3 = __float2half_rn(v.w - __half2float(h3));
    __half2 H0 = __halves2half2(h0, h1);
    __half2 H1 = __halves2half2(h2, h3);
    __half2 L0 = __halves2half2(l0, l1);
    __half2 L1 = __halves2half2(l2, l3);
    uint2 uh = make_uint2(*reinterpret_cast<uint32_t*>(&H0), *reinterpret_cast<uint32_t*>(&H1));
    uint2 ul = make_uint2(*reinterpret_cast<uint32_t*>(&L0), *reinterpret_cast<uint32_t*>(&L1));
    *reinterpret_cast<uint2*>(ph) = uh;
    *reinterpret_cast<uint2*>(pl) = ul;
}

// A = [x | prev_c]  ->  g_Ah/g_Al [B, 1024]
__global__ __launch_bounds__(256) void convA_kernel(const float* __restrict__ X,
                                                    const float* __restrict__ Hr) {
    int i = blockIdx.x * 256 + threadIdx.x;   // over BS/4 (exact)
    int b = i >> 7;
    int s = (i & 127) * 4;
    float4 xv = *reinterpret_cast<const float4*>(&X[(size_t)b * S_DIM + s]);
    float4 hv = *reinterpret_cast<const float4*>(&Hr[(size_t)b * S_DIM + s]);
    size_t o = (size_t)b * KTOT + s;
    split4_store(xv, &g_Ah[o],         &g_Al[o]);
    split4_store(hv, &g_Ah[o + S_DIM], &g_Al[o + S_DIM]);
}

// Bperm[j, k] with j = s*4 + gate  (orig col n = gate*512 + s), k over [W|R]
// (validated in R14)
__global__ __launch_bounds__(256) void convB_kernel(const float* __restrict__ Wk,
                                                    const float* __restrict__ Rk,
                                                    size_t outOff) {
    __shared__ float t[32][33];
    int tx = threadIdx.x & 31, ty = threadIdx.x >> 5;   // 32x8
    int k0 = blockIdx.x * 32, n0 = blockIdx.y * 32;
    #pragma unroll
    for (int r = ty; r < 32; r += 8) {
        int kk = k0 + r;
        float v = (kk < S_DIM) ? Wk[(size_t)kk * NS + n0 + tx]
                               : Rk[(size_t)(kk - S_DIM) * NS + n0 + tx];
        t[r][tx] = v;
    }
    __syncthreads();
    #pragma unroll
    for (int r = ty; r < 32; r += 8) {
        int n = n0 + r;
        int j = ((n & (S_DIM - 1)) << 2) | (n >> 9);   // gate-interleaved permutation
        g_Bh[outOff + (size_t)j * KTOT + k0 + tx] = __float2half_rn(t[tx][r]);
    }
}

// ---------------------------------------------------------------------------
// Fused GEMM + LSTM cell.
// Mainloop + g_z store: byte-identical to R14 (validated). Then, in the same
// kernel: __syncthreads(), read back this CTA's own z-tile from g_z (L2-hot),
// apply the R14-validated permuted cell decode, and write h/c directly.
// ---------------------------------------------------------------------------
#define KC 64
#define NCHUNK (KTOT / KC)          // 16
#define TILE_B 16384                // 128 rows x 128 bytes
#define STAGE_B (3 * TILE_B)        // Ah, Al, Bh = 48 KB
#define SMEM_GEMM (2 * STAGE_B)     // 96 KB

#define OFF_AH 0
#define OFF_AL 16384
#define OFF_BH 32768

__device__ __forceinline__ void gemm_load_stage(uint32_t stage, int c, int bm, int bn, int tid,
                                                const __half* __restrict__ Bh) {
    const int kc = c * KC;
    #pragma unroll
    for (int i = 0; i < 4; i++) {
        int idx = tid + (i << 8);          // 0..1023
        int row = idx >> 3;
        int c16 = idx & 7;
        uint32_t so = SWZ((uint32_t)(row * 128 + c16 * 16));
        size_t ga = (size_t)(bm + row) * KTOT + kc + c16 * 8;
        size_t gb = (size_t)(bn + row) * KTOT + kc + c16 * 8;
        CP_ASYNC16(stage + OFF_AH + so, g_Ah + ga);
        CP_ASYNC16(stage + OFF_AL + so, g_Al + ga);
        CP_ASYNC16(stage + OFF_BH + so, Bh + gb);
    }
}

__global__ __launch_bounds__(256, 2) void lstm_gemm_fused(
    size_t bOff,
    const float* __restrict__ ctm1,   // prev_h[layer] (NNI swap: this is c_tm1)
    const float* __restrict__ bias,   // [4S]
    float* __restrict__ h_out, float* __restrict__ c_out) {
    extern __shared__ char smem[];
    const uint32_t sb = smem_u32(smem);
    const int tid = threadIdx.x;
    const int wid = tid >> 5, lid = tid & 31;
    const int bm = blockIdx.y * 128;
    const int bn = blockIdx.x * 128;
    const int s_base = bn >> 2;       // 32 s-values per tile

    const __half* Bh = g_Bh + bOff;

    const int wm = (wid >> 1) * 32;   // warp m-origin: 0,32,64,96
    const int wn = (wid & 1) * 64;    // warp n-origin: 0,64

    const int a_row = lid & 15;
    const int a_kb  = (lid >> 4) * 16;
    const int b_row = ((lid >> 4) << 3) + (lid & 7);
    const int b_kb  = ((lid >> 3) & 1) * 16;

    float acc[2][8][4];
    #pragma unroll
    for (int mt = 0; mt < 2; mt++)
        #pragma unroll
        for (int nt = 0; nt < 8; nt++)
            #pragma unroll
            for (int q = 0; q < 4; q++) acc[mt][nt][q] = 0.f;

    gemm_load_stage(sb, 0, bm, bn, tid, Bh);
    CP_COMMIT();

    for (int c = 0; c < NCHUNK; c++) {
        const int s = c & 1;
        if (c + 1 < NCHUNK) {
            gemm_load_stage(sb + (s ^ 1) * STAGE_B, c + 1, bm, bn, tid, Bh);
            CP_COMMIT();
            CP_WAIT1();
        } else {
            CP_WAIT0();
        }
        __syncthreads();

        const uint32_t st = sb + s * STAGE_B;
        #pragma unroll
        for (int kk = 0; kk < 4; kk++) {
            const uint32_t kbb = kk * 32;
            uint32_t ah[2][4], al[2][4];
            #pragma unroll
            for (int mt = 0; mt < 2; mt++) {
                uint32_t o = SWZ((uint32_t)((wm + mt * 16 + a_row) * 128) + kbb + a_kb);
                LDSM_X4(ah[mt], st + OFF_AH + o);
                LDSM_X4(al[mt], st + OFF_AL + o);
            }
            uint32_t bh[4][4];
            #pragma unroll
            for (int np = 0; np < 4; np++) {
                uint32_t o = SWZ((uint32_t)((wn + np * 16 + b_row) * 128) + kbb + b_kb);
                LDSM_X4(bh[np], st + OFF_BH + o);
            }
            #pragma unroll
            for (int mt = 0; mt < 2; mt++)
                #pragma unroll
                for (int np = 0; np < 4; np++) {
                    MMA16816(acc[mt][np * 2],     ah[mt], bh[np][0], bh[np][1]);
                    MMA16816(acc[mt][np * 2],     al[mt], bh[np][0], bh[np][1]);
                    MMA16816(acc[mt][np * 2 + 1], ah[mt], bh[np][2], bh[np][3]);
                    MMA16816(acc[mt][np * 2 + 1], al[mt], bh[np][2], bh[np][3]);
                }
        }
        __syncthreads();
    }

    // z-tile store to g_z (R14-validated mapping)
    {
        const int er = lid >> 2;
        const int ec = (lid & 3) * 2;
        #pragma unroll
        for (int mt = 0; mt < 2; mt++) {
            #pragma unroll
            for (int nt = 0; nt < 8; nt++) {
                size_t row = (size_t)(bm + wm + mt * 16 + er);
                int col = bn + wn + nt * 8 + ec;
                *reinterpret_cast<float2*>(&g_z[row * NS + col]) =
                    make_float2(acc[mt][nt][0], acc[mt][nt][1]);
                *reinterpret_cast<float2*>(&g_z[(row + 8) * NS + col]) =
                    make_float2(acc[mt][nt][2], acc[mt][nt][3]);
            }
        }
    }
    __syncthreads();   // block-scope visibility of this CTA's g_z tile

    // Fused cell: read back own tile (L2-hot) with R14-validated decode.
    // 128 rows x 8 s-quads = 1024 items; 4 per thread.
    #pragma unroll
    for (int it = 0; it < 4; it++) {
        int item = tid + it * 256;           // 0..1023
        int row  = item >> 3;                // 0..127
        int q    = item & 7;                 // s-quad within tile
        int s0l  = q * 4;                    // local s: 0,4,...,28
        int sg0  = s_base + s0l;             // global s of quad start
        int b    = bm + row;

        const float* zr = g_z + (size_t)b * NS + bn + s0l * 4;  // 4 s x 4 gates
        float4 ct = *reinterpret_cast<const float4*>(&ctm1[(size_t)b * S_DIM + sg0]);

        float4 c4, h4;
        #pragma unroll
        for (int e = 0; e < 4; e++) {
            int sg = sg0 + e;
            float4 z4 = *reinterpret_cast<const float4*>(&zr[e * 4]);  // (i,f,g,o)
            float zi = z4.x + __ldg(&bias[sg]);
            float zf = z4.y + __ldg(&bias[S_DIM + sg]);
            float zg = z4.z + __ldg(&bias[2 * S_DIM + sg]);
            float zo = z4.w + __ldg(&bias[3 * S_DIM + sg]);
            float ctv = (e == 0) ? ct.x : (e == 1) ? ct.y : (e == 2) ? ct.z : ct.w;
            float cc = sigf(zf) * ctv + sigf(zi) * tanhf(zg);
            float hh = sigf(zo) * tanhf(cc);
            (&c4.x)[e] = cc;
            (&h4.x)[e] = hh;
        }

        size_t o = (size_t)b * S_DIM + sg0;
        *reinterpret_cast<float4*>(&h_out[o]) = h4;
        *reinterpret_cast<float4*>(&c_out[o]) = c4;
    }
}

// ---------------------------------------------------------------------------
// Launch
// ---------------------------------------------------------------------------
extern "C" void kernel_launch(void* const* d_in, const int* in_sizes, int n_in,
                              void* d_out, int out_size) {
    const float* inputs  = (const float*)d_in[0];   // [B, S]
    const float* prev_c  = (const float*)d_in[1];   // [L, B, S]
    const float* prev_h  = (const float*)d_in[2];   // [L, B, S]
    const float* kernels = (const float*)d_in[3];   // [L, S, 4S]
    const float* recks   = (const float*)d_in[4];   // [L, S, 4S]
    const float* biases  = (const float*)d_in[5];   // [L, 4S]
    float* out = (float*)d_out;                     // [L, 2, B, S]

    cudaFuncSetAttribute(lstm_gemm_fused, cudaFuncAttributeMaxDynamicSharedMemorySize, SMEM_GEMM);

    dim3 gB(KTOT / 32, NS / 32);           // (32, 64)
    dim3 gG(NS / 128, B_DIM / 128);        // (16, 128)
    int convA_blocks = (BS / 4) / 256;     // 8192

    // Weight conversion (both layers)
    convB_kernel<<<gB, 256>>>(kernels, recks, (size_t)0);
    convB_kernel<<<gB, 256>>>(kernels + (size_t)S_DIM * NS, recks + (size_t)S_DIM * NS,
                              (size_t)NS * KTOT);

    // ---- Layer 0 (fused GEMM + cell) ----
    convA_kernel<<<convA_blocks, 256>>>(inputs, prev_c);
    lstm_gemm_fused<<<gG, 256, SMEM_GEMM>>>((size_t)0, prev_h, biases,
                                            out + 0 * (size_t)BS,   // h0
                                            out + 1 * (size_t)BS);  // c0
    // ---- Layer 1 ---- x = c0 (validated convA path, no chaining)
    convA_kernel<<<convA_blocks, 256>>>(out + 1 * (size_t)BS, prev_c + (size_t)BS);
    lstm_gemm_fused<<<gG, 256, SMEM_GEMM>>>((size_t)NS * KTOT, prev_h + (size_t)BS, biases + NS,
                                            out + 2 * (size_t)BS,   // h1
                                            out + 3 * (size_t)BS);  // c1
}

// round 17
// speedup vs baseline: 1.5989x; 1.5989x over previous
#include <cuda_runtime.h>
#include <cuda_fp16.h>
#include <cstdint>

// Problem constants
#define B_DIM 16384
#define S_DIM 512
#define NS    2048   // 4*S
#define KTOT  1024   // 2*S (x-half + recurrent-half)
#define BS    (B_DIM * S_DIM)  // 8388608

// ---------------------------------------------------------------------------
// Device scratch (static __device__: allocation-guard safe)
// ---------------------------------------------------------------------------
__device__ float g_z[(size_t)B_DIM * NS];                 // 128 MiB (permuted cols)
__device__ __half g_Ah[(size_t)B_DIM * KTOT];             // 32 MiB
__device__ __half g_Bh[(size_t)2 * NS * KTOT];            // 8 MiB  per-layer [Nperm,K]

// ---------------------------------------------------------------------------
// PTX helpers — sm_80+ features only (compute_103 virtual target safe)
// ---------------------------------------------------------------------------
__device__ __forceinline__ uint32_t smem_u32(const void* p) {
    uint32_t a;
    asm("{ .reg .u64 t; cvta.to.shared.u64 t, %1; cvt.u32.u64 %0, t; }"
        : "=r"(a) : "l"(p));
    return a;
}

#define CP_ASYNC16(dst_u32, src_ptr) \
    asm volatile("cp.async.cg.shared.global [%0], [%1], 16;" \
                 :: "r"((uint32_t)(dst_u32)), "l"((const void*)(src_ptr)) : "memory")
#define CP_COMMIT() asm volatile("cp.async.commit_group;" ::: "memory")
#define CP_WAIT1()  asm volatile("cp.async.wait_group 1;" ::: "memory")
#define CP_WAIT0()  asm volatile("cp.async.wait_group 0;" ::: "memory")

// SW128 swizzle on byte offset within a 1024-aligned tile (128B rows)
#define SWZ(o) ((o) ^ (((o) >> 3) & 0x70))

#define LDSM_X4(r, addr) \
    asm volatile("ldmatrix.sync.aligned.m8n8.x4.shared.b16 {%0,%1,%2,%3}, [%4];" \
                 : "=r"((r)[0]), "=r"((r)[1]), "=r"((r)[2]), "=r"((r)[3]) \
                 : "r"((uint32_t)(addr)))

#define MMA16816(d, a, b0, b1) \
    asm volatile("mma.sync.aligned.m16n8k16.row.col.f32.f16.f16.f32 " \
                 "{%0,%1,%2,%3}, {%4,%5,%6,%7}, {%8,%9}, {%0,%1,%2,%3};" \
                 : "+f"((d)[0]), "+f"((d)[1]), "+f"((d)[2]), "+f"((d)[3]) \
                 : "r"((a)[0]), "r"((a)[1]), "r"((a)[2]), "r"((a)[3]), \
                   "r"(b0), "r"(b1))

__device__ __forceinline__ float sigf(float x) { return 1.f / (1.f + expf(-x)); }

// ---------------------------------------------------------------------------
// Conversion kernels (fp16 truncation for A and B)
// ---------------------------------------------------------------------------
__device__ __forceinline__ void cvt4_store(float4 v, __half* ph) {
    __half2 H0 = __halves2half2(__float2half_rn(v.x), __float2half_rn(v.y));
    __half2 H1 = __halves2half2(__float2half_rn(v.z), __float2half_rn(v.w));
    uint2 uh = make_uint2(*reinterpret_cast<uint32_t*>(&H0), *reinterpret_cast<uint32_t*>(&H1));
    *reinterpret_cast<uint2*>(ph) = uh;
}

// A = [x | prev_c]  ->  g_Ah [B, 1024]
__global__ __launch_bounds__(256) void convA_kernel(const float* __restrict__ X,
                                                    const float* __restrict__ Hr) {
    int i = blockIdx.x * 256 + threadIdx.x;   // over BS/4 (exact)
    int b = i >> 7;
    int s = (i & 127) * 4;
    float4 xv = *reinterpret_cast<const float4*>(&X[(size_t)b * S_DIM + s]);
    float4 hv = *reinterpret_cast<const float4*>(&Hr[(size_t)b * S_DIM + s]);
    size_t o = (size_t)b * KTOT + s;
    cvt4_store(xv, &g_Ah[o]);
    cvt4_store(hv, &g_Ah[o + S_DIM]);
}

// Bperm[j, k] with j = s*4 + gate  (orig col n = gate*512 + s), k over [W|R]
// (validated in R14)
__global__ __launch_bounds__(256) void convB_kernel(const float* __restrict__ Wk,
                                                    const float* __restrict__ Rk,
                                                    size_t outOff) {
    __shared__ float t[32][33];
    int tx = threadIdx.x & 31, ty = threadIdx.x >> 5;   // 32x8
    int k0 = blockIdx.x * 32, n0 = blockIdx.y * 32;
    #pragma unroll
    for (int r = ty; r < 32; r += 8) {
        int kk = k0 + r;
        float v = (kk < S_DIM) ? Wk[(size_t)kk * NS + n0 + tx]
                               : Rk[(size_t)(kk - S_DIM) * NS + n0 + tx];
        t[r][tx] = v;
    }
    __syncthreads();
    #pragma unroll
    for (int r = ty; r < 32; r += 8) {
        int n = n0 + r;
        int j = ((n & (S_DIM - 1)) << 2) | (n >> 9);   // gate-interleaved permutation
        g_Bh[outOff + (size_t)j * KTOT + k0 + tx] = __float2half_rn(t[tx][r]);
    }
}

// ---------------------------------------------------------------------------
// mma.sync GEMM (R14 skeleton, single product Ah*Bh):
// g_z[16384, 2048] = A[16384,1024] * Bmat[2048,1024]^T  (Bmat = permuted rows)
// ---------------------------------------------------------------------------
#define KC 64
#define NCHUNK (KTOT / KC)          // 16
#define TILE_B 16384                // 128 rows x 128 bytes
#define STAGE_B (2 * TILE_B)        // Ah, Bh = 32 KB
#define SMEM_GEMM (2 * STAGE_B)     // 64 KB

#define OFF_AH 0
#define OFF_BH 16384

__device__ __forceinline__ void gemm_load_stage(uint32_t stage, int c, int bm, int bn, int tid,
                                                const __half* __restrict__ Bh) {
    const int kc = c * KC;
    #pragma unroll
    for (int i = 0; i < 4; i++) {
        int idx = tid + (i << 8);          // 0..1023
        int row = idx >> 3;
        int c16 = idx & 7;
        uint32_t so = SWZ((uint32_t)(row * 128 + c16 * 16));
        size_t ga = (size_t)(bm + row) * KTOT + kc + c16 * 8;
        size_t gb = (size_t)(bn + row) * KTOT + kc + c16 * 8;
        CP_ASYNC16(stage + OFF_AH + so, g_Ah + ga);
        CP_ASYNC16(stage + OFF_BH + so, Bh + gb);
    }
}

__global__ __launch_bounds__(256, 2) void lstm_gemm_mma(size_t bOff) {
    extern __shared__ char smem[];
    const uint32_t sb = smem_u32(smem);
    const int tid = threadIdx.x;
    const int wid = tid >> 5, lid = tid & 31;
    const int bm = blockIdx.y * 128;
    const int bn = blockIdx.x * 128;

    const __half* Bh = g_Bh + bOff;

    const int wm = (wid >> 1) * 32;   // warp m-origin: 0,32,64,96
    const int wn = (wid & 1) * 64;    // warp n-origin: 0,64

    const int a_row = lid & 15;
    const int a_kb  = (lid >> 4) * 16;
    const int b_row = ((lid >> 4) << 3) + (lid & 7);
    const int b_kb  = ((lid >> 3) & 1) * 16;

    float acc[2][8][4];
    #pragma unroll
    for (int mt = 0; mt < 2; mt++)
        #pragma unroll
        for (int nt = 0; nt < 8; nt++)
            #pragma unroll
            for (int q = 0; q < 4; q++) acc[mt][nt][q] = 0.f;

    gemm_load_stage(sb, 0, bm, bn, tid, Bh);
    CP_COMMIT();

    for (int c = 0; c < NCHUNK; c++) {
        const int s = c & 1;
        if (c + 1 < NCHUNK) {
            gemm_load_stage(sb + (s ^ 1) * STAGE_B, c + 1, bm, bn, tid, Bh);
            CP_COMMIT();
            CP_WAIT1();
        } else {
            CP_WAIT0();
        }
        __syncthreads();

        const uint32_t st = sb + s * STAGE_B;
        #pragma unroll
        for (int kk = 0; kk < 4; kk++) {
            const uint32_t kbb = kk * 32;
            uint32_t ah[2][4];
            #pragma unroll
            for (int mt = 0; mt < 2; mt++) {
                uint32_t o = SWZ((uint32_t)((wm + mt * 16 + a_row) * 128) + kbb + a_kb);
                LDSM_X4(ah[mt], st + OFF_AH + o);
            }
            uint32_t bh[4][4];
            #pragma unroll
            for (int np = 0; np < 4; np++) {
                uint32_t o = SWZ((uint32_t)((wn + np * 16 + b_row) * 128) + kbb + b_kb);
                LDSM_X4(bh[np], st + OFF_BH + o);
            }
            #pragma unroll
            for (int mt = 0; mt < 2; mt++)
                #pragma unroll
                for (int np = 0; np < 4; np++) {
                    MMA16816(acc[mt][np * 2],     ah[mt], bh[np][0], bh[np][1]);
                    MMA16816(acc[mt][np * 2 + 1], ah[mt], bh[np][2], bh[np][3]);
                }
        }
        __syncthreads();
    }

    // Epilogue (R14-validated): lane l -> rows (l>>2), (l>>2)+8; cols (l&3)*2, +1
    const int er = lid >> 2;
    const int ec = (lid & 3) * 2;
    #pragma unroll
    for (int mt = 0; mt < 2; mt++) {
        #pragma unroll
        for (int nt = 0; nt < 8; nt++) {
            size_t row = (size_t)(bm + wm + mt * 16 + er);
            int col = bn + wn + nt * 8 + ec;
            *reinterpret_cast<float2*>(&g_z[row * NS + col]) =
                make_float2(acc[mt][nt][0], acc[mt][nt][1]);
            *reinterpret_cast<float2*>(&g_z[(row + 8) * NS + col]) =
                make_float2(acc[mt][nt][2], acc[mt][nt][3]);
        }
    }
}

// ---------------------------------------------------------------------------
// Elementwise LSTM cell over PERMUTED z (validated in R14):
// z[b, s*4 + gate] -> contiguous float4 per s holds (zi, zf, zg, zo).
// ---------------------------------------------------------------------------
__global__ __launch_bounds__(256) void lstm_cell_perm_kernel(
    const float* __restrict__ Ctm1, const float* __restrict__ bias,
    float* __restrict__ h_out, float* __restrict__ c_out) {
    int idx = blockIdx.x * blockDim.x + threadIdx.x;
    if (idx >= BS / 4) return;
    int b = idx >> 7;
    int s0 = (idx & 127) * 4;

    const float* zr = g_z + (size_t)b * NS + (size_t)s0 * 4;   // 4 s-values x 4 gates
    float4 ct = *reinterpret_cast<const float4*>(&Ctm1[(size_t)b * S_DIM + s0]);

    float4 c, h;
    #pragma unroll
    for (int e = 0; e < 4; e++) {
        int s = s0 + e;
        float4 z4 = *reinterpret_cast<const float4*>(&zr[e * 4]);  // (i,f,g,o)
        float zi = z4.x + __ldg(&bias[s]);
        float zf = z4.y + __ldg(&bias[S_DIM + s]);
        float zg = z4.z + __ldg(&bias[2 * S_DIM + s]);
        float zo = z4.w + __ldg(&bias[3 * S_DIM + s]);
        float ctv = (e == 0) ? ct.x : (e == 1) ? ct.y : (e == 2) ? ct.z : ct.w;
        float cc = sigf(zf) * ctv + sigf(zi) * tanhf(zg);
        float hh = sigf(zo) * tanhf(cc);
        (&c.x)[e] = cc;
        (&h.x)[e] = hh;
    }

    size_t o = (size_t)b * S_DIM + s0;
    *reinterpret_cast<float4*>(&h_out[o]) = h;
    *reinterpret_cast<float4*>(&c_out[o]) = c;
}

// ---------------------------------------------------------------------------
// Launch (R14 structure)
// ---------------------------------------------------------------------------
extern "C" void kernel_launch(void* const* d_in, const int* in_sizes, int n_in,
                              void* d_out, int out_size) {
    const float* inputs  = (const float*)d_in[0];   // [B, S]
    const float* prev_c  = (const float*)d_in[1];   // [L, B, S]
    const float* prev_h  = (const float*)d_in[2];   // [L, B, S]
    const float* kernels = (const float*)d_in[3];   // [L, S, 4S]
    const float* recks   = (const float*)d_in[4];   // [L, S, 4S]
    const float* biases  = (const float*)d_in[5];   // [L, 4S]
    float* out = (float*)d_out;                     // [L, 2, B, S]

    cudaFuncSetAttribute(lstm_gemm_mma, cudaFuncAttributeMaxDynamicSharedMemorySize, SMEM_GEMM);

    dim3 gB(KTOT / 32, NS / 32);           // (32, 64)
    dim3 gG(NS / 128, B_DIM / 128);        // (16, 128)
    int convA_blocks = (BS / 4) / 256;     // 8192
    int cell_blocks  = (BS / 4 + 255) / 256;

    // Weight conversion (both layers)
    convB_kernel<<<gB, 256>>>(kernels, recks, (size_t)0);
    convB_kernel<<<gB, 256>>>(kernels + (size_t)S_DIM * NS, recks + (size_t)S_DIM * NS,
                              (size_t)NS * KTOT);

    // ---- Layer 0 ----
    convA_kernel<<<convA_blocks, 256>>>(inputs, prev_c);
    lstm_gemm_mma<<<gG, 256, SMEM_GEMM>>>((size_t)0);
    lstm_cell_perm_kernel<<<cell_blocks, 256>>>(prev_h, biases,
                                                out + 0 * (size_t)BS,   // h0
                                                out + 1 * (size_t)BS);  // c0
    // ---- Layer 1 ---- x = c0
    convA_kernel<<<convA_blocks, 256>>>(out + 1 * (size_t)BS, prev_c + (size_t)BS);
    lstm_gemm_mma<<<gG, 256, SMEM_GEMM>>>((size_t)NS * KTOT);
    lstm_cell_perm_kernel<<<cell_blocks, 256>>>(prev_h + (size_t)BS, biases + NS,
                                                out + 2 * (size_t)BS,   // h1
                                                out + 3 * (size_t)BS);  // c1
}